// round 5
// baseline (speedup 1.0000x reference)
#include <cuda_runtime.h>
#include <cuda_bf16.h>
#include <math.h>

// Problem constants (fixed-shape problem)
#define MAXN 50000
#define MAXE 800000
#define FDIM 128
#define CDIM 8
#define TP   65   // padded row stride of transposed A tile (At[k][r], r<64)

// packed fp32x2 FMA (Blackwell FFMA2) — only reachable via PTX fma.rn.f32x2
#define FMA2(acc, a, b) \
    asm("fma.rn.f32x2 %0, %1, %2, %0;" : "+l"(acc) : "l"(a), "l"(b))

// ---------------- scratch (static __device__, no allocation) ----------------
__device__ int   d_is64;             // edge_index dtype flag (runtime-detected)
__device__ int   d_cnt[MAXN];        // edge count per target node (no self loop)
__device__ int   d_offs[MAXN + 1];   // CSR offsets
__device__ int   d_cursor[MAXN];     // scatter cursors
__device__ float d_dinv[MAXN];       // 1/sqrt(deg) incl. self loop
__device__ int   d_csr[MAXE];        // source node per edge, sorted by target
__device__ float d_bufA[(size_t)MAXN * FDIM];  // ping
__device__ float d_bufB[(size_t)MAXN * FDIM];  // pong

// ---------------- edge dtype detection ----------------
// If edge_index is int64 (little-endian), every odd 32-bit word is a high half
// of a value < 50000 -> 0. If int32, odd words are random node ids.
__global__ void detect_kernel(const unsigned int* __restrict__ w) {
    if (threadIdx.x == 0 && blockIdx.x == 0) {
        unsigned int acc = 0;
        #pragma unroll
        for (int i = 0; i < 64; i++) acc |= w[2 * i + 1];
        d_is64 = (acc == 0) ? 1 : 0;
    }
}

// ---------------- CSR construction (reads edge_index directly) ----------------
__global__ void zero_cnt_kernel(int n) {
    int i = blockIdx.x * blockDim.x + threadIdx.x;
    if (i < n) d_cnt[i] = 0;
}

__global__ void hist_kernel(const int* __restrict__ w, int e) {
    int i = blockIdx.x * blockDim.x + threadIdx.x;
    if (i < e) {
        int c = d_is64 ? w[2 * (e + i)] : w[e + i];   // low word if int64
        atomicAdd(&d_cnt[c], 1);
    }
}

// single-block exclusive scan of d_cnt -> d_offs (n up to 50000)
__global__ void scan_kernel(int n) {
    __shared__ int warp_sums[32];
    __shared__ int s_carry;
    const int tid = threadIdx.x;
    const int lane = tid & 31, wid = tid >> 5;
    if (tid == 0) { d_offs[0] = 0; s_carry = 0; }
    __syncthreads();
    for (int base = 0; base < n; base += 1024) {
        int i = base + tid;
        int v = (i < n) ? d_cnt[i] : 0;
        int x = v;
        #pragma unroll
        for (int o = 1; o < 32; o <<= 1) {
            int t = __shfl_up_sync(0xffffffffu, x, o);
            if (lane >= o) x += t;
        }
        if (lane == 31) warp_sums[wid] = x;
        __syncthreads();
        if (wid == 0) {
            int s = warp_sums[lane];
            #pragma unroll
            for (int o = 1; o < 32; o <<= 1) {
                int t = __shfl_up_sync(0xffffffffu, s, o);
                if (lane >= o) s += t;
            }
            warp_sums[lane] = s;
        }
        __syncthreads();
        int prefix = s_carry + (wid > 0 ? warp_sums[wid - 1] : 0) + x;
        if (i < n) d_offs[i + 1] = prefix;
        __syncthreads();
        if (tid == 0) s_carry += warp_sums[31];
        __syncthreads();
    }
}

__global__ void prep_kernel(int n) {
    int i = blockIdx.x * blockDim.x + threadIdx.x;
    if (i < n) {
        d_dinv[i] = rsqrtf((float)(d_cnt[i] + 1));  // +1 self loop
        d_cursor[i] = d_offs[i];
    }
}

__global__ void scatter_kernel(const int* __restrict__ w, int e) {
    int i = blockIdx.x * blockDim.x + threadIdx.x;
    if (i < e) {
        int is64 = d_is64;
        int c = is64 ? w[2 * (e + i)] : w[e + i];
        int r = is64 ? w[2 * i]       : w[i];
        int p = atomicAdd(&d_cursor[c], 1);
        d_csr[p] = r;
    }
}

// ---------------- GEMM (FFMA2): out[r][:] = dinv[r] * (A[r][:] @ W) ----------------
// block: 256 threads = 8 warps. Tile: 64 rows x 128 cols, K=128.
// Warp w owns cols [w*16, w*16+16). Lane l owns rows {l, l+32}.
// A tile stored TRANSPOSED (At[k][r], pad 65) -> conflict-free lane-consecutive LDS.
// b loads are warp-broadcast LDS.128. FFMA2 is the binding pipe.
__global__ void __launch_bounds__(256) gemm_scaled_kernel(
    const float* __restrict__ A, const float* __restrict__ W,
    float* __restrict__ out, int n)
{
    extern __shared__ float sh[];
    float* At = sh;                 // [128][TP]
    float* Ws = sh + 128 * TP;      // [128][128]
    const int tid = threadIdx.x;
    const int row0 = blockIdx.x * 64;

    // load W (4096 float4, 16 per thread)
    {
        const float4* Wv = (const float4*)W;
        float4* Wsv = (float4*)Ws;
        #pragma unroll
        for (int i = 0; i < 16; i++) Wsv[tid + i * 256] = Wv[tid + i * 256];
    }
    // load A tile coalesced, store transposed (2048 float4, 8 per thread)
    #pragma unroll
    for (int i = 0; i < 8; i++) {
        int idx = tid + i * 256;          // float4 index in 64x32 tile
        int r  = idx >> 5;                // 0..63
        int kq = (idx & 31) * 4;          // k base
        float4 v = make_float4(0.f, 0.f, 0.f, 0.f);
        int gr = row0 + r;
        if (gr < n) v = ((const float4*)A)[(size_t)gr * 32 + (idx & 31)];
        At[(kq + 0) * TP + r] = v.x;
        At[(kq + 1) * TP + r] = v.y;
        At[(kq + 2) * TP + r] = v.z;
        At[(kq + 3) * TP + r] = v.w;
    }
    __syncthreads();

    const int w = tid >> 5, l = tid & 31;
    const float* bcol = Ws + w * 16;

    unsigned long long acc[16];           // rows {l, l+32} x 8 col-pairs
    #pragma unroll
    for (int j = 0; j < 16; j++) acc[j] = 0ull;

    #pragma unroll 4
    for (int k = 0; k < 128; k++) {
        float a0 = At[k * TP + l];
        float a1 = At[k * TP + 32 + l];
        unsigned long long a0p, a1p;
        asm("mov.b64 %0, {%1, %1};" : "=l"(a0p) : "f"(a0));
        asm("mov.b64 %0, {%1, %1};" : "=l"(a1p) : "f"(a1));
        const ulonglong2* bp = (const ulonglong2*)(bcol + k * 128);
        ulonglong2 b01 = bp[0], b23 = bp[1], b45 = bp[2], b67 = bp[3];
        FMA2(acc[0], a0p, b01.x);  FMA2(acc[1], a0p, b01.y);
        FMA2(acc[2], a0p, b23.x);  FMA2(acc[3], a0p, b23.y);
        FMA2(acc[4], a0p, b45.x);  FMA2(acc[5], a0p, b45.y);
        FMA2(acc[6], a0p, b67.x);  FMA2(acc[7], a0p, b67.y);
        FMA2(acc[8],  a1p, b01.x); FMA2(acc[9],  a1p, b01.y);
        FMA2(acc[10], a1p, b23.x); FMA2(acc[11], a1p, b23.y);
        FMA2(acc[12], a1p, b45.x); FMA2(acc[13], a1p, b45.y);
        FMA2(acc[14], a1p, b67.x); FMA2(acc[15], a1p, b67.y);
    }

    // epilogue: unpack, scale by dinv, store 16 cols per row
    #pragma unroll
    for (int half = 0; half < 2; half++) {
        int r = row0 + half * 32 + l;
        if (r < n) {
            float s = d_dinv[r];
            float o[16];
            #pragma unroll
            for (int j = 0; j < 8; j++) {
                float lo, hi;
                asm("mov.b64 {%0, %1}, %2;" : "=f"(lo), "=f"(hi) : "l"(acc[half * 8 + j]));
                o[2 * j] = lo * s;  o[2 * j + 1] = hi * s;
            }
            float* dst = out + (size_t)r * 128 + w * 16;
            #pragma unroll
            for (int q = 0; q < 4; q++)
                *(float4*)(dst + q * 4) = make_float4(o[4*q], o[4*q+1], o[4*q+2], o[4*q+3]);
        }
    }
}

// ---------------- Aggregation: warp per node, 4-way unrolled gather ----------------
// out[c][:] = dinv[c] * ( g[c][:] + sum_{edges r->c} g[r][:] ) + bias[:]
__device__ __forceinline__ void gather_rows(
    const float* __restrict__ g, int node, int lane, float4& acc)
{
    float4 acc1 = make_float4(0.f,0.f,0.f,0.f);
    float4 acc2 = make_float4(0.f,0.f,0.f,0.f);
    float4 acc3 = make_float4(0.f,0.f,0.f,0.f);
    const int s = d_offs[node], e = d_offs[node + 1];
    for (int i = s; i < e; i += 32) {
        int idx = (i + lane < e) ? d_csr[i + lane] : 0;
        int cnt = min(32, e - i);
        int j = 0;
        for (; j + 4 <= cnt; j += 4) {
            int r0 = __shfl_sync(0xffffffffu, idx, j);
            int r1 = __shfl_sync(0xffffffffu, idx, j + 1);
            int r2 = __shfl_sync(0xffffffffu, idx, j + 2);
            int r3 = __shfl_sync(0xffffffffu, idx, j + 3);
            float4 v0 = *(const float4*)(g + (size_t)r0 * 128 + lane * 4);
            float4 v1 = *(const float4*)(g + (size_t)r1 * 128 + lane * 4);
            float4 v2 = *(const float4*)(g + (size_t)r2 * 128 + lane * 4);
            float4 v3 = *(const float4*)(g + (size_t)r3 * 128 + lane * 4);
            acc.x  += v0.x; acc.y  += v0.y; acc.z  += v0.z; acc.w  += v0.w;
            acc1.x += v1.x; acc1.y += v1.y; acc1.z += v1.z; acc1.w += v1.w;
            acc2.x += v2.x; acc2.y += v2.y; acc2.z += v2.z; acc2.w += v2.w;
            acc3.x += v3.x; acc3.y += v3.y; acc3.z += v3.z; acc3.w += v3.w;
        }
        for (; j < cnt; j++) {
            int r = __shfl_sync(0xffffffffu, idx, j);
            float4 v = *(const float4*)(g + (size_t)r * 128 + lane * 4);
            acc.x += v.x; acc.y += v.y; acc.z += v.z; acc.w += v.w;
        }
    }
    acc.x += acc1.x + acc2.x + acc3.x;
    acc.y += acc1.y + acc2.y + acc3.y;
    acc.z += acc1.z + acc2.z + acc3.z;
    acc.w += acc1.w + acc2.w + acc3.w;
}

__global__ void agg_kernel(const float* __restrict__ g, const float* __restrict__ bias,
                           float* __restrict__ outh, int n)
{
    const int warp = (blockIdx.x * blockDim.x + threadIdx.x) >> 5;
    const int lane = threadIdx.x & 31;
    if (warp >= n) return;
    const int node = warp;

    float4 acc = *(const float4*)(g + (size_t)node * 128 + lane * 4);  // self loop
    gather_rows(g, node, lane, acc);

    const float dv = d_dinv[node];
    float4 b = *(const float4*)(bias + lane * 4);
    float4 o = make_float4(acc.x * dv + b.x, acc.y * dv + b.y,
                           acc.z * dv + b.z, acc.w * dv + b.w);
    *(float4*)(outh + (size_t)node * 128 + lane * 4) = o;
}

// ---------------- Aggregation 2 fused with final FC (128 -> 8) ----------------
__global__ void agg_fc_kernel(const float* __restrict__ g, const float* __restrict__ b2,
                              const float* __restrict__ Wfc, const float* __restrict__ bfc,
                              float* __restrict__ out, int n)
{
    __shared__ float sWt[CDIM * 128];   // transposed: sWt[j*128 + f]
    __shared__ float sb[CDIM];
    const int tid = threadIdx.x;
    for (int i = tid; i < CDIM * 128; i += blockDim.x) {
        int f = i >> 3, j = i & 7;      // i = f*8 + j in source layout
        sWt[j * 128 + f] = Wfc[i];
    }
    if (tid < CDIM) sb[tid] = bfc[tid];
    __syncthreads();

    const int warp = (blockIdx.x * blockDim.x + tid) >> 5;
    const int lane = tid & 31;
    if (warp >= n) return;
    const int node = warp;

    float4 acc = *(const float4*)(g + (size_t)node * 128 + lane * 4);
    gather_rows(g, node, lane, acc);

    const float dv = d_dinv[node];
    float4 bb = *(const float4*)(b2 + lane * 4);
    float h0 = acc.x * dv + bb.x;
    float h1 = acc.y * dv + bb.y;
    float h2 = acc.z * dv + bb.z;
    float h3 = acc.w * dv + bb.w;

    float p[CDIM];
    #pragma unroll
    for (int j = 0; j < CDIM; j++) {
        float4 w = *(const float4*)(sWt + j * 128 + lane * 4);
        p[j] = h0 * w.x + h1 * w.y + h2 * w.z + h3 * w.w;
    }
    #pragma unroll
    for (int o = 16; o >= 1; o >>= 1)
        #pragma unroll
        for (int j = 0; j < CDIM; j++)
            p[j] += __shfl_xor_sync(0xffffffffu, p[j], o);

    if (lane == 0) {
        float4 o0 = make_float4(p[0] + sb[0], p[1] + sb[1], p[2] + sb[2], p[3] + sb[3]);
        float4 o1 = make_float4(p[4] + sb[4], p[5] + sb[5], p[6] + sb[6], p[7] + sb[7]);
        *(float4*)(out + (size_t)node * CDIM) = o0;
        *(float4*)(out + (size_t)node * CDIM + 4) = o1;
    }
}

// ---------------- launch ----------------
extern "C" void kernel_launch(void* const* d_in, const int* in_sizes, int n_in,
                              void* d_out, int out_size)
{
    const float* x   = (const float*)d_in[0];
    const int*   ei  = (const int*)  d_in[1];   // int32 OR int64 (runtime-detected)
    const float* W1  = (const float*)d_in[2];
    const float* b1  = (const float*)d_in[3];
    const float* W2  = (const float*)d_in[4];
    const float* b2  = (const float*)d_in[5];
    const float* Wfc = (const float*)d_in[6];
    const float* bfc = (const float*)d_in[7];
    float* out = (float*)d_out;

    const int N = in_sizes[0] / FDIM;
    const int E = in_sizes[1] / 2;

    static const size_t GEMM_SMEM = (128 * TP + 128 * 128) * sizeof(float);  // ~96.5 KB
    cudaFuncSetAttribute(gemm_scaled_kernel,
                         cudaFuncAttributeMaxDynamicSharedMemorySize, (int)GEMM_SMEM);

    float* bufA;  cudaGetSymbolAddress((void**)&bufA, d_bufA);
    float* bufB;  cudaGetSymbolAddress((void**)&bufB, d_bufB);

    const int nb_N = (N + 255) / 256;
    const int nb_E = (E + 255) / 256;
    const int nb_W = (N + 7) / 8;          // warp per node, 8 warps/block
    const int nb_G = (N + 63) / 64;

    detect_kernel<<<1, 32>>>((const unsigned int*)ei);
    zero_cnt_kernel<<<nb_N, 256>>>(N);
    hist_kernel<<<nb_E, 256>>>(ei, E);
    scan_kernel<<<1, 1024>>>(N);
    prep_kernel<<<nb_N, 256>>>(N);
    scatter_kernel<<<nb_E, 256>>>(ei, E);

    gemm_scaled_kernel<<<nb_G, 256, GEMM_SMEM>>>(x, W1, bufA, N);
    agg_kernel<<<nb_W, 256>>>(bufA, b1, bufB, N);

    gemm_scaled_kernel<<<nb_G, 256, GEMM_SMEM>>>(bufB, W2, bufA, N);
    agg_fc_kernel<<<nb_W, 256>>>(bufA, b2, Wfc, bfc, out, N);
}

// round 6
// speedup vs baseline: 1.2307x; 1.2307x over previous
#include <cuda_runtime.h>
#include <cuda_bf16.h>
#include <math.h>

// Problem constants (fixed-shape problem)
#define MAXN 50000
#define MAXE 800000
#define FDIM 128
#define CDIM 8
#define MAXB ((MAXN + 255) / 256)   // max scan blocks (196)

// ---------------- scratch (static __device__, no allocation) ----------------
__device__ int   d_is64;             // edge_index dtype flag (runtime-detected)
__device__ int   d_cnt[MAXN];        // edge count per target node (no self loop)
__device__ int   d_offs[MAXN + 1];   // CSR offsets
__device__ int   d_cursor[MAXN];     // scatter cursors
__device__ float d_dinv[MAXN];       // 1/sqrt(deg) incl. self loop
__device__ int   d_csr[MAXE];        // source node per edge, sorted by target
__device__ int   d_bsum[MAXB];       // per-block count sums
__device__ int   d_boff[MAXB];       // per-block exclusive offsets
__device__ float d_bufA[(size_t)MAXN * FDIM];  // ping
__device__ float d_bufB[(size_t)MAXN * FDIM];  // pong

// ---------------- edge dtype detection ----------------
// If edge_index is int64 (little-endian), every odd 32-bit word is a high half
// of a value < 50000 -> 0. If int32, odd words are random node ids.
__global__ void detect_kernel(const unsigned int* __restrict__ w) {
    if (threadIdx.x == 0 && blockIdx.x == 0) {
        unsigned int acc = 0;
        #pragma unroll
        for (int i = 0; i < 64; i++) acc |= w[2 * i + 1];
        d_is64 = (acc == 0) ? 1 : 0;
    }
}

// ---------------- CSR construction ----------------
__global__ void zero_cnt_kernel(int n) {
    int i = blockIdx.x * blockDim.x + threadIdx.x;
    if (i < n) d_cnt[i] = 0;
}

__global__ void hist_kernel(const int* __restrict__ w, int e) {
    int i = blockIdx.x * blockDim.x + threadIdx.x;
    if (i < e) {
        int c = d_is64 ? w[2 * (e + i)] : w[e + i];   // low word if int64
        atomicAdd(&d_cnt[c], 1);
    }
}

// ---- decoupled scan: pass 1 — per-block sum of 256 counts ----
__global__ void bsum_kernel(int n) {
    const int b = blockIdx.x;
    const int tid = threadIdx.x;
    int i = b * 256 + tid;
    int v = (i < n) ? d_cnt[i] : 0;
    #pragma unroll
    for (int o = 16; o; o >>= 1) v += __shfl_xor_sync(0xffffffffu, v, o);
    __shared__ int ws[8];
    if ((tid & 31) == 0) ws[tid >> 5] = v;
    __syncthreads();
    if (tid == 0) {
        int s = 0;
        #pragma unroll
        for (int j = 0; j < 8; j++) s += ws[j];
        d_bsum[b] = s;
    }
}

// ---- pass 2 — single-block exclusive scan of nb block sums (nb <= 1024) ----
__global__ void bscan_kernel(int nb) {
    const int tid = threadIdx.x, lane = tid & 31, wid = tid >> 5;
    int v = (tid < nb) ? d_bsum[tid] : 0;
    int x = v;
    #pragma unroll
    for (int o = 1; o < 32; o <<= 1) {
        int t = __shfl_up_sync(0xffffffffu, x, o);
        if (lane >= o) x += t;
    }
    __shared__ int ws[32];
    if (lane == 31) ws[wid] = x;
    __syncthreads();
    if (wid == 0) {
        int s = ws[lane];
        #pragma unroll
        for (int o = 1; o < 32; o <<= 1) {
            int t = __shfl_up_sync(0xffffffffu, s, o);
            if (lane >= o) s += t;
        }
        ws[lane] = s;
    }
    __syncthreads();
    int incl = x + (wid ? ws[wid - 1] : 0);
    if (tid < nb) d_boff[tid] = incl - v;   // exclusive
}

// ---- pass 3 — per-block scan + apply (offs, cursor, dinv) ----
__global__ void scan_apply_kernel(int n) {
    const int b = blockIdx.x;
    const int tid = threadIdx.x, lane = tid & 31, wid = tid >> 5;
    int i = b * 256 + tid;
    int v = (i < n) ? d_cnt[i] : 0;
    int x = v;
    #pragma unroll
    for (int o = 1; o < 32; o <<= 1) {
        int t = __shfl_up_sync(0xffffffffu, x, o);
        if (lane >= o) x += t;
    }
    __shared__ int ws[8];
    if (lane == 31) ws[wid] = x;
    __syncthreads();
    if (wid == 0 && lane < 8) {
        int s = ws[lane];
        #pragma unroll
        for (int o = 1; o < 8; o <<= 1) {
            int t = __shfl_up_sync(0x000000ffu, s, o);
            if (lane >= o) s += t;
        }
        ws[lane] = s;
    }
    __syncthreads();
    int incl = x + (wid ? ws[wid - 1] : 0) + d_boff[b];
    if (i < n) {
        d_offs[i + 1] = incl;
        d_cursor[i]   = incl - v;
        d_dinv[i]     = rsqrtf((float)(v + 1));   // +1 self loop
        if (i == 0) d_offs[0] = 0;
    }
}

__global__ void scatter_kernel(const int* __restrict__ w, int e) {
    int i = blockIdx.x * blockDim.x + threadIdx.x;
    if (i < e) {
        int is64 = d_is64;
        int c = is64 ? w[2 * (e + i)] : w[e + i];
        int r = is64 ? w[2 * i]       : w[i];
        int p = atomicAdd(&d_cursor[c], 1);
        d_csr[p] = r;
    }
}

// ---------------- GEMM: out[r][:] = dinv[r] * (A[r][:] @ W)  (128x128 W) ----------------
// block: 256 threads, tile 64 rows x 128 cols, full K=128.  (proven R4 version)
__global__ void __launch_bounds__(256) gemm_scaled_kernel(
    const float* __restrict__ A, const float* __restrict__ W,
    float* __restrict__ out, int n)
{
    extern __shared__ float sh[];
    float* As = sh;               // 64*128
    float* Ws = sh + 64 * 128;    // 128*128
    const int tid = threadIdx.x;
    const int row0 = blockIdx.x * 64;

    {
        const float4* Wv = (const float4*)W;
        float4* Wsv = (float4*)Ws;
        #pragma unroll
        for (int i = 0; i < 16; i++) Wsv[tid + i * 256] = Wv[tid + i * 256];
    }
    {
        float4* Asv = (float4*)As;
        #pragma unroll
        for (int i = 0; i < 8; i++) {
            int idx = tid + i * 256;
            int r = row0 + (idx >> 5);
            float4 v = make_float4(0.f, 0.f, 0.f, 0.f);
            if (r < n) v = ((const float4*)A)[(size_t)r * 32 + (idx & 31)];
            Asv[idx] = v;
        }
    }
    __syncthreads();

    const int tc = tid & 31;
    const int tr = tid >> 5;
    float acc[8][4];
    #pragma unroll
    for (int i = 0; i < 8; i++)
        #pragma unroll
        for (int j = 0; j < 4; j++) acc[i][j] = 0.f;

    const float* AsBase = As + (tr * 8) * 128;
    const float* WsBase = Ws + tc * 4;
    #pragma unroll 4
    for (int k = 0; k < 128; k++) {
        float4 b = *(const float4*)(WsBase + k * 128);
        #pragma unroll
        for (int i = 0; i < 8; i++) {
            float a = AsBase[i * 128 + k];
            acc[i][0] += a * b.x;
            acc[i][1] += a * b.y;
            acc[i][2] += a * b.z;
            acc[i][3] += a * b.w;
        }
    }

    #pragma unroll
    for (int i = 0; i < 8; i++) {
        int r = row0 + tr * 8 + i;
        if (r < n) {
            float s = d_dinv[r];
            float4 v = make_float4(acc[i][0] * s, acc[i][1] * s, acc[i][2] * s, acc[i][3] * s);
            *(float4*)(out + (size_t)r * 128 + tc * 4) = v;
        }
    }
}

// ---------------- Aggregation: warp per node (proven R4 version) ----------------
__global__ void agg_kernel(const float* __restrict__ g, const float* __restrict__ bias,
                           float* __restrict__ outh, int n)
{
    const int warp = (blockIdx.x * blockDim.x + threadIdx.x) >> 5;
    const int lane = threadIdx.x & 31;
    if (warp >= n) return;
    const int node = warp;

    float4 acc = *(const float4*)(g + (size_t)node * 128 + lane * 4);  // self loop
    const int s = d_offs[node], e = d_offs[node + 1];
    for (int i = s; i < e; i += 32) {
        int idx = (i + lane < e) ? d_csr[i + lane] : 0;
        int cnt = min(32, e - i);
        for (int j = 0; j < cnt; j++) {
            int r = __shfl_sync(0xffffffffu, idx, j);
            float4 v = *(const float4*)(g + (size_t)r * 128 + lane * 4);
            acc.x += v.x; acc.y += v.y; acc.z += v.z; acc.w += v.w;
        }
    }
    const float dv = d_dinv[node];
    float4 b = *(const float4*)(bias + lane * 4);
    float4 o = make_float4(acc.x * dv + b.x, acc.y * dv + b.y,
                           acc.z * dv + b.z, acc.w * dv + b.w);
    *(float4*)(outh + (size_t)node * 128 + lane * 4) = o;
}

// ---------------- Aggregation 2 fused with final FC (128 -> 8) ----------------
__global__ void agg_fc_kernel(const float* __restrict__ g, const float* __restrict__ b2,
                              const float* __restrict__ Wfc, const float* __restrict__ bfc,
                              float* __restrict__ out, int n)
{
    __shared__ float sWt[CDIM * 128];   // transposed: sWt[j*128 + f]
    __shared__ float sb[CDIM];
    const int tid = threadIdx.x;
    for (int i = tid; i < CDIM * 128; i += blockDim.x) {
        int f = i >> 3, j = i & 7;      // i = f*8 + j in source layout
        sWt[j * 128 + f] = Wfc[i];
    }
    if (tid < CDIM) sb[tid] = bfc[tid];
    __syncthreads();

    const int warp = (blockIdx.x * blockDim.x + tid) >> 5;
    const int lane = tid & 31;
    if (warp >= n) return;
    const int node = warp;

    float4 acc = *(const float4*)(g + (size_t)node * 128 + lane * 4);
    const int s = d_offs[node], e = d_offs[node + 1];
    for (int i = s; i < e; i += 32) {
        int idx = (i + lane < e) ? d_csr[i + lane] : 0;
        int cnt = min(32, e - i);
        for (int j = 0; j < cnt; j++) {
            int r = __shfl_sync(0xffffffffu, idx, j);
            float4 v = *(const float4*)(g + (size_t)r * 128 + lane * 4);
            acc.x += v.x; acc.y += v.y; acc.z += v.z; acc.w += v.w;
        }
    }
    const float dv = d_dinv[node];
    float4 bb = *(const float4*)(b2 + lane * 4);
    float h0 = acc.x * dv + bb.x;
    float h1 = acc.y * dv + bb.y;
    float h2 = acc.z * dv + bb.z;
    float h3 = acc.w * dv + bb.w;

    float p[CDIM];
    #pragma unroll
    for (int j = 0; j < CDIM; j++) {
        float4 w = *(const float4*)(sWt + j * 128 + lane * 4);
        p[j] = h0 * w.x + h1 * w.y + h2 * w.z + h3 * w.w;
    }
    #pragma unroll
    for (int o = 16; o >= 1; o >>= 1)
        #pragma unroll
        for (int j = 0; j < CDIM; j++)
            p[j] += __shfl_xor_sync(0xffffffffu, p[j], o);

    if (lane == 0) {
        float4 o0 = make_float4(p[0] + sb[0], p[1] + sb[1], p[2] + sb[2], p[3] + sb[3]);
        float4 o1 = make_float4(p[4] + sb[4], p[5] + sb[5], p[6] + sb[6], p[7] + sb[7]);
        *(float4*)(out + (size_t)node * CDIM) = o0;
        *(float4*)(out + (size_t)node * CDIM + 4) = o1;
    }
}

// ---------------- launch ----------------
extern "C" void kernel_launch(void* const* d_in, const int* in_sizes, int n_in,
                              void* d_out, int out_size)
{
    const float* x   = (const float*)d_in[0];
    const int*   ei  = (const int*)  d_in[1];   // int32 OR int64 (runtime-detected)
    const float* W1  = (const float*)d_in[2];
    const float* b1  = (const float*)d_in[3];
    const float* W2  = (const float*)d_in[4];
    const float* b2  = (const float*)d_in[5];
    const float* Wfc = (const float*)d_in[6];
    const float* bfc = (const float*)d_in[7];
    float* out = (float*)d_out;

    const int N = in_sizes[0] / FDIM;
    const int E = in_sizes[1] / 2;

    static const size_t GEMM_SMEM = (64 * 128 + 128 * 128) * sizeof(float);  // 96 KB
    cudaFuncSetAttribute(gemm_scaled_kernel,
                         cudaFuncAttributeMaxDynamicSharedMemorySize, (int)GEMM_SMEM);

    float* bufA;  cudaGetSymbolAddress((void**)&bufA, d_bufA);
    float* bufB;  cudaGetSymbolAddress((void**)&bufB, d_bufB);

    const int nb_N = (N + 255) / 256;      // also = scan block count
    const int nb_E = (E + 255) / 256;
    const int nb_W = (N + 7) / 8;          // warp per node, 8 warps/block
    const int nb_G = (N + 63) / 64;

    detect_kernel<<<1, 32>>>((const unsigned int*)ei);
    zero_cnt_kernel<<<nb_N, 256>>>(N);
    hist_kernel<<<nb_E, 256>>>(ei, E);
    bsum_kernel<<<nb_N, 256>>>(N);
    bscan_kernel<<<1, 1024>>>(nb_N);
    scan_apply_kernel<<<nb_N, 256>>>(N);
    scatter_kernel<<<nb_E, 256>>>(ei, E);

    gemm_scaled_kernel<<<nb_G, 256, GEMM_SMEM>>>(x, W1, bufA, N);
    agg_kernel<<<nb_W, 256>>>(bufA, b1, bufB, N);

    gemm_scaled_kernel<<<nb_G, 256, GEMM_SMEM>>>(bufB, W2, bufA, N);
    agg_fc_kernel<<<nb_W, 256>>>(bufA, b2, Wfc, bfc, out, N);
}